// round 7
// baseline (speedup 1.0000x reference)
#include <cuda_runtime.h>
#include <cuda_bf16.h>
#include <cstdint>

// Problem constants (fixed: B=8, S=4096, D=512, CD=4096)
#define N_ROWS 32768
#define DIM    512
#define KCODES 4096

// main kernel tiling (fp8: 1 byte/elem)
#define M_CTA   128                 // rows per unit
#define NHALF   2048                // codes per unit (2-way code split)
#define N_TILE  128                 // codes per B stage
#define BKB     128                 // fp8 K elems per chunk (=128B rows)
#define CHUNKS  (DIM / BKB)         // 4
#define NT      (NHALF / N_TILE)    // 16
#define ITERS   (NT * CHUNKS)       // 64
#define GRID    ((N_ROWS / M_CTA) * 2)  // 512 units
#define NTHR    256

// smem: [align 1KB][A 64KB][B 3x16KB][merge 8KB]
#define A_BYTES   (M_CTA * DIM)              // 65536
#define BSTAGE    (N_TILE * BKB)             // 16384
#define MERGE_OFF (A_BYTES + 3 * BSTAGE)     // 114688
#define DYN_SMEM  (1024 + MERGE_OFF + 8192)  // 123904

// Scratch (device globals; no allocation allowed)
__device__ __align__(16) float  g_c2[KCODES];        // 0.5*||c||^2 exact fp32
__device__ int    g_cand[N_ROWS * 8];                // top-4 per half, 8/row
__device__ double g_loss;
__device__ __align__(16) uint8_t g_x8[N_ROWS * DIM];   // 16MB e4m3
__device__ __align__(16) uint8_t g_cb8[KCODES * DIM];  // 2MB  e4m3

// ---------------------------------------------------------------------------
// PTX helpers (sm_80/89-level only: cp.async, ldmatrix, mma.sync fp8)
// ---------------------------------------------------------------------------
__device__ __forceinline__ uint32_t smem_u32(const void* p) {
    uint32_t a;
    asm("{ .reg .u64 t; cvta.to.shared.u64 t, %1; cvt.u32.u64 %0, t; }"
        : "=r"(a) : "l"(p));
    return a;
}

#define CP16(dst, src) \
    asm volatile("cp.async.cg.shared.global [%0], [%1], 16;" \
                 :: "r"(dst), "l"(src) : "memory")

#define LDSM4(r0, r1, r2, r3, addr) \
    asm volatile("ldmatrix.sync.aligned.m8n8.x4.shared.b16 {%0,%1,%2,%3}, [%4];" \
                 : "=r"(r0), "=r"(r1), "=r"(r2), "=r"(r3) : "r"(addr))

#define MMA_FP8(d, a, b) \
    asm volatile("mma.sync.aligned.m16n8k32.row.col.f32.e4m3.e4m3.f32 " \
                 "{%0,%1,%2,%3}, {%4,%5,%6,%7}, {%8,%9}, {%0,%1,%2,%3};" \
                 : "+f"((d)[0]), "+f"((d)[1]), "+f"((d)[2]), "+f"((d)[3]) \
                 : "r"((a)[0]), "r"((a)[1]), "r"((a)[2]), "r"((a)[3]), \
                   "r"((b)[0]), "r"((b)[1]))

// pack 4 fp32 -> 4 e4m3 bytes (pair order consistent across A and B, so
// within-pair ordering cancels in the dot product)
__device__ __forceinline__ uint32_t to_e4m3x4(float4 v) {
    uint16_t lo, hi;
    asm("cvt.rn.satfinite.e4m3x2.f32 %0, %1, %2;" : "=h"(lo) : "f"(v.y), "f"(v.x));
    asm("cvt.rn.satfinite.e4m3x2.f32 %0, %1, %2;" : "=h"(hi) : "f"(v.w), "f"(v.z));
    return (uint32_t)lo | ((uint32_t)hi << 16);
}

// sorted ascending top-4 insert
__device__ __forceinline__ void t4_insert(float (&v)[4], int (&ix)[4],
                                          float s, int i) {
    if (s < v[3]) {
        if (s < v[1]) {
            if (s < v[0]) {
                v[3]=v[2]; ix[3]=ix[2]; v[2]=v[1]; ix[2]=ix[1];
                v[1]=v[0]; ix[1]=ix[0]; v[0]=s; ix[0]=i;
            } else {
                v[3]=v[2]; ix[3]=ix[2]; v[2]=v[1]; ix[2]=ix[1];
                v[1]=s; ix[1]=i;
            }
        } else {
            if (s < v[2]) { v[3]=v[2]; ix[3]=ix[2]; v[2]=s; ix[2]=i; }
            else          { v[3]=s; ix[3]=i; }
        }
    }
}

// ---------------------------------------------------------------------------
// Prep kernels: e4m3 conversion + 0.5||c||^2 + loss zero
// ---------------------------------------------------------------------------
__global__ void prep_x(const float* __restrict__ x) {
    int i = blockIdx.x * blockDim.x + threadIdx.x;  // 8192 x 512
    ((uint32_t*)g_x8)[i] = to_e4m3x4(((const float4*)x)[i]);
}

__global__ void prep_cb(const float* __restrict__ cb) {
    int n = blockIdx.x, t = threadIdx.x;  // 4096 x 128
    float4 v = ((const float4*)(cb + (size_t)n * DIM))[t];
    ((uint32_t*)g_cb8)[(size_t)n * 128 + t] = to_e4m3x4(v);

    float s = v.x * v.x + v.y * v.y + v.z * v.z + v.w * v.w;
    #pragma unroll
    for (int off = 16; off > 0; off >>= 1)
        s += __shfl_down_sync(0xffffffffu, s, off);
    __shared__ float ws[4];
    if ((t & 31) == 0) ws[t >> 5] = s;
    __syncthreads();
    if (t == 0) {
        g_c2[n] = 0.5f * (ws[0] + ws[1] + ws[2] + ws[3]);
        if (n == 0) g_loss = 0.0;
    }
}

// ---------------------------------------------------------------------------
// Kernel 1: fp8 HMMA distance GEMM + fused per-row top-4 candidates.
// Unit = (128 rows) x (2048 codes: half of codebook). 512 units.
// Score(row, code) = 0.5||c||^2 - x.c (same argmin ordering as dist^2).
// A (128 rows x 512 fp8) resident in smem; B streamed, 3-stage cp.async ring.
// ---------------------------------------------------------------------------
__global__ __launch_bounds__(NTHR)
void cand_kernel() {
    extern __shared__ char dsm[];
    const uint32_t sraw = smem_u32(dsm);
    const uint32_t sb   = (sraw + 1023u) & ~1023u;
    char* base = dsm + (sb - sraw);
    const uint32_t Ab = sb;
    const uint32_t Bb = sb + A_BYTES;

    const int tid  = threadIdx.x;
    const int lane = tid & 31, wid = tid >> 5;
    const int warpM = wid & 3, warpN = wid >> 2;
    const int half = blockIdx.x & 1;
    const int m0   = (blockIdx.x >> 1) * M_CTA;
    const int ncb0 = half * NHALF;

    // ldmatrix per-thread address constants (rows are 128B, SW within row)
    const uint32_t arow = (uint32_t)((lane & 7) + ((lane & 8) ? 8 : 0));
    const uint32_t asel = (lane & 16) ? 16u : 0u;
    const uint32_t axr  = (arow & 7u) << 4;
    const uint32_t abase0 = (uint32_t)(warpM * 32 + (int)arow) * 128u;
    const uint32_t abase1 = abase0 + 16u * 128u;
    const uint32_t brow = (uint32_t)((lane & 7) + ((lane & 16) ? 8 : 0));
    const uint32_t bsel = (lane & 8) ? 16u : 0u;
    const uint32_t bxr  = (brow & 7u) << 4;
    const uint32_t bstart = (uint32_t)(warpN * 64 + (int)brow) * 128u;

    // ---- prologue: stage A fully (group 0), B it=0 (g1), B it=1 (g2) ------
    {
        #pragma unroll
        for (int j = 0; j < 16; j++) {
            int e = tid + j * 256;            // 4096 16B segs
            int ch = e >> 10, rem = e & 1023, row = rem >> 3, seg = rem & 7;
            const uint8_t* src = g_x8 + (size_t)(m0 + row) * DIM + ch * BKB + seg * 16;
            uint32_t dst = Ab + (uint32_t)ch * 16384u + (uint32_t)row * 128u +
                           (((uint32_t)seg * 16u) ^ (((uint32_t)row & 7u) << 4));
            CP16(dst, src);
        }
        asm volatile("cp.async.commit_group;" ::: "memory");
        #pragma unroll
        for (int pre = 0; pre < 2; pre++) {
            int nt2 = pre >> 2, kc2 = pre & 3, s2 = pre % 3;
            #pragma unroll
            for (int j = 0; j < 4; j++) {
                int e = tid + j * 256;
                int row = e >> 3, seg = e & 7;
                const uint8_t* src =
                    g_cb8 + (size_t)(ncb0 + nt2 * N_TILE + row) * DIM + kc2 * BKB + seg * 16;
                uint32_t dst = Bb + (uint32_t)s2 * BSTAGE + (uint32_t)row * 128u +
                               (((uint32_t)seg * 16u) ^ (((uint32_t)row & 7u) << 4));
                CP16(dst, src);
            }
            asm volatile("cp.async.commit_group;" ::: "memory");
        }
    }

    float acc[2][8][4];
    #pragma unroll
    for (int mt = 0; mt < 2; mt++)
        #pragma unroll
        for (int p = 0; p < 8; p++)
            #pragma unroll
            for (int c = 0; c < 4; c++) acc[mt][p][c] = 0.f;

    float t4v[4][4];
    int   t4i[4][4];
    #pragma unroll
    for (int r = 0; r < 4; r++)
        #pragma unroll
        for (int j = 0; j < 4; j++) { t4v[r][j] = 3.4e38f; t4i[r][j] = 0; }

    // ---- main loop ---------------------------------------------------------
    for (int it = 0; it < ITERS; it++) {
        const int nt = it >> 2, kc = it & 3, s = it % 3;
        asm volatile("cp.async.wait_group 1;" ::: "memory");
        __syncthreads();

        // prefetch B for it+2
        const int it2 = it + 2;
        if (it2 < ITERS) {
            const int nt2 = it2 >> 2, kc2 = it2 & 3, s2 = it2 % 3;
            #pragma unroll
            for (int j = 0; j < 4; j++) {
                int e = tid + j * 256;
                int row = e >> 3, seg = e & 7;
                const uint8_t* src =
                    g_cb8 + (size_t)(ncb0 + nt2 * N_TILE + row) * DIM + kc2 * BKB + seg * 16;
                uint32_t dst = Bb + (uint32_t)s2 * BSTAGE + (uint32_t)row * 128u +
                               (((uint32_t)seg * 16u) ^ (((uint32_t)row & 7u) << 4));
                CP16(dst, src);
            }
        }
        asm volatile("cp.async.commit_group;" ::: "memory");

        // compute this 128B k-chunk: 4 k32 steps
        const uint32_t Achunk = Ab + (uint32_t)kc * 16384u;
        const uint32_t Bs     = Bb + (uint32_t)s * BSTAGE;
        #pragma unroll
        for (int ks = 0; ks < 4; ks++) {
            const uint32_t koA = (((uint32_t)(ks * 32)) + asel) ^ axr;
            uint32_t a0[4], a1[4];
            LDSM4(a0[0], a0[1], a0[2], a0[3], Achunk + abase0 + koA);
            LDSM4(a1[0], a1[1], a1[2], a1[3], Achunk + abase1 + koA);
            const uint32_t koB = (((uint32_t)(ks * 32)) + bsel) ^ bxr;
            uint32_t bb[8][2];
            #pragma unroll
            for (int p = 0; p < 4; p++) {
                uint32_t r0, r1, r2, r3;
                LDSM4(r0, r1, r2, r3, Bs + bstart + (uint32_t)p * 2048u + koB);
                bb[2 * p][0] = r0; bb[2 * p][1] = r1;
                bb[2 * p + 1][0] = r2; bb[2 * p + 1][1] = r3;
            }
            #pragma unroll
            for (int p = 0; p < 8; p++) {
                MMA_FP8(acc[0][p], a0, bb[p]);
                MMA_FP8(acc[1][p], a1, bb[p]);
            }
        }

        // fold finished code tile into running top-4, reset accumulators
        if (kc == CHUNKS - 1) {
            #pragma unroll
            for (int mt = 0; mt < 2; mt++) {
                #pragma unroll
                for (int p = 0; p < 8; p++) {
                    const int ng = ncb0 + nt * N_TILE + warpN * 64 + p * 8 + 2 * (lane & 3);
                    const float2 c2 = __ldg((const float2*)(g_c2 + ng));
                    t4_insert(t4v[mt * 2 + 0], t4i[mt * 2 + 0], c2.x - acc[mt][p][0], ng);
                    t4_insert(t4v[mt * 2 + 0], t4i[mt * 2 + 0], c2.y - acc[mt][p][1], ng + 1);
                    t4_insert(t4v[mt * 2 + 1], t4i[mt * 2 + 1], c2.x - acc[mt][p][2], ng);
                    t4_insert(t4v[mt * 2 + 1], t4i[mt * 2 + 1], c2.y - acc[mt][p][3], ng + 1);
                    acc[mt][p][0] = 0.f; acc[mt][p][1] = 0.f;
                    acc[mt][p][2] = 0.f; acc[mt][p][3] = 0.f;
                }
            }
        }
    }

    // ---- merge: quad (shfl) -> cross-warpN (smem) --------------------------
    #pragma unroll
    for (int rs = 0; rs < 4; rs++) {
        #pragma unroll
        for (int delta = 1; delta <= 2; delta <<= 1) {
            float ov[4]; int oi[4];
            #pragma unroll
            for (int j = 0; j < 4; j++) {
                ov[j] = __shfl_xor_sync(0xffffffffu, t4v[rs][j], delta);
                oi[j] = __shfl_xor_sync(0xffffffffu, t4i[rs][j], delta);
            }
            #pragma unroll
            for (int j = 0; j < 4; j++) t4_insert(t4v[rs], t4i[rs], ov[j], oi[j]);
        }
    }

    __syncthreads();
    float* mv = (float*)(base + MERGE_OFF);
    int*   mi = (int*)(base + MERGE_OFF + 4096);
    if ((lane & 3) == 0) {
        #pragma unroll
        for (int rs = 0; rs < 4; rs++) {
            int row_local = warpM * 32 + (rs >> 1) * 16 + ((rs & 1) << 3) + (lane >> 2);
            int idx = (warpN * 128 + row_local) * 4;
            #pragma unroll
            for (int j = 0; j < 4; j++) { mv[idx + j] = t4v[rs][j]; mi[idx + j] = t4i[rs][j]; }
        }
    }
    __syncthreads();
    if (tid < 128) {
        float v[4]; int ix[4];
        #pragma unroll
        for (int j = 0; j < 4; j++) { v[j] = mv[tid * 4 + j]; ix[j] = mi[tid * 4 + j]; }
        #pragma unroll
        for (int j = 0; j < 4; j++)
            t4_insert(v, ix, mv[(128 + tid) * 4 + j], mi[(128 + tid) * 4 + j]);
        #pragma unroll
        for (int j = 0; j < 4; j++)
            g_cand[(size_t)(m0 + tid) * 8 + half * 4 + j] = ix[j];
    }
}

// ---------------------------------------------------------------------------
// Kernel 2: exact fp32 rescore of 8 candidates, argmin (tie -> lower index),
// gather nearest, accumulate loss. out_near base only 8B aligned -> float2.
// ---------------------------------------------------------------------------
__global__ void rescore_gather_kernel(const float* __restrict__ x,
                                      const float* __restrict__ cb,
                                      float* __restrict__ out_enc,
                                      float* __restrict__ out_near) {
    const int row = blockIdx.x;   // 32768
    const int t   = threadIdx.x;  // 128
    __shared__ float sdot[4][8];
    __shared__ int   s_enc;
    __shared__ float ws[4];

    int cand[8];
    #pragma unroll
    for (int j = 0; j < 8; j++) cand[j] = g_cand[(size_t)row * 8 + j];

    const float4 xv = ((const float4*)(x + (size_t)row * DIM))[t];
    #pragma unroll
    for (int j = 0; j < 8; j++) {
        const float4 cv = ((const float4*)(cb + (size_t)cand[j] * DIM))[t];
        float p = xv.x * cv.x + xv.y * cv.y + xv.z * cv.z + xv.w * cv.w;
        #pragma unroll
        for (int off = 16; off > 0; off >>= 1)
            p += __shfl_down_sync(0xffffffffu, p, off);
        if ((t & 31) == 0) sdot[t >> 5][j] = p;
    }
    __syncthreads();
    if (t == 0) {
        float bs = 3.4e38f; int bi = 0x7fffffff;
        #pragma unroll
        for (int j = 0; j < 8; j++) {
            float dot = sdot[0][j] + sdot[1][j] + sdot[2][j] + sdot[3][j];
            float s = g_c2[cand[j]] - dot;
            if (s < bs || (s == bs && cand[j] < bi)) { bs = s; bi = cand[j]; }
        }
        s_enc = bi;
        out_enc[row] = (float)bi;
    }
    __syncthreads();
    const int enc = s_enc;

    const float4 c = ((const float4*)(cb + (size_t)enc * DIM))[t];
    float2* orow = (float2*)(out_near + (size_t)row * DIM);
    orow[2 * t]     = make_float2(c.x, c.y);
    orow[2 * t + 1] = make_float2(c.z, c.w);
    float dx = xv.x - c.x, dy = xv.y - c.y, dz = xv.z - c.z, dw = xv.w - c.w;
    float s = dx * dx + dy * dy + dz * dz + dw * dw;
    #pragma unroll
    for (int off = 16; off > 0; off >>= 1)
        s += __shfl_down_sync(0xffffffffu, s, off);
    if ((t & 31) == 0) ws[t >> 5] = s;
    __syncthreads();
    if (t == 0) {
        double tot = (double)ws[0] + (double)ws[1] + (double)ws[2] + (double)ws[3];
        atomicAdd(&g_loss, tot);
    }
}

__global__ void finalize_kernel(float* __restrict__ out_losses) {
    double mean = g_loss / ((double)N_ROWS * (double)DIM);
    out_losses[0] = (float)mean;
    out_losses[1] = (float)mean;
}

// ---------------------------------------------------------------------------
// Output layout (float32): [0,32768) encoding; [32768,32770) losses;
// [32770, ...) nearest (base only 8B aligned).
// ---------------------------------------------------------------------------
extern "C" void kernel_launch(void* const* d_in, const int* in_sizes, int n_in,
                              void* d_out, int out_size) {
    const float* x  = (const float*)d_in[0];
    const float* cb = (const float*)d_in[1];
    if (n_in >= 2 && in_sizes[0] == KCODES * DIM && in_sizes[1] == N_ROWS * DIM) {
        const float* tmp = x; x = cb; cb = tmp;
    }

    float* out        = (float*)d_out;
    float* out_enc    = out;
    float* out_losses = out + N_ROWS;
    float* out_near   = out + N_ROWS + 2;

    static int smem_set = 0;
    if (!smem_set) {
        cudaFuncSetAttribute(cand_kernel,
                             cudaFuncAttributeMaxDynamicSharedMemorySize, DYN_SMEM);
        smem_set = 1;
    }

    prep_x<<<8192, 512>>>(x);
    prep_cb<<<KCODES, 128>>>(cb);
    cand_kernel<<<GRID, NTHR, DYN_SMEM>>>();
    rescore_gather_kernel<<<N_ROWS, 128>>>(x, cb, out_enc, out_near);
    finalize_kernel<<<1, 1>>>(out_losses);
}

// round 8
// speedup vs baseline: 1.4251x; 1.4251x over previous
#include <cuda_runtime.h>
#include <cuda_bf16.h>
#include <cstdint>

// Problem constants (fixed: B=8, S=4096, D=512, CD=4096)
#define N_ROWS 32768
#define DIM    512
#define KCODES 4096

// main kernel tiling (int8: 1 byte/elem)
#define M_CTA   128                 // rows per unit
#define NHALF   2048                // codes per unit (2-way code split)
#define N_TILE  128                 // codes per B stage
#define BKB     128                 // int8 K elems per chunk (=128B rows)
#define CHUNKS  (DIM / BKB)         // 4
#define NT      (NHALF / N_TILE)    // 16
#define ITERS   (NT * CHUNKS)       // 64
#define GRID    ((N_ROWS / M_CTA) * 2)  // 512 units
#define NTHR    256

#define QS 23.0f                    // int8 quant scale (127/5.5 ~ 23)

// smem: [align 1KB][A 64KB][B 3x16KB][merge 8KB]
#define A_BYTES   (M_CTA * DIM)              // 65536
#define BSTAGE    (N_TILE * BKB)             // 16384
#define MERGE_OFF (A_BYTES + 3 * BSTAGE)     // 114688
#define DYN_SMEM  (1024 + MERGE_OFF + 8192)  // 123904

// Scratch (device globals; no allocation allowed)
__device__ __align__(16) float  g_c2[KCODES];    // exact 0.5*||c||^2 (rescore)
__device__ __align__(16) float  g_c2s[KCODES];   // 0.5*||c||^2 * QS^2 (filter)
__device__ int    g_cand[N_ROWS * 8];            // top-4 per half, 8/row
__device__ double g_loss;
__device__ __align__(16) uint8_t g_x8[N_ROWS * DIM];   // 16MB s8
__device__ __align__(16) uint8_t g_cb8[KCODES * DIM];  // 2MB  s8

// ---------------------------------------------------------------------------
// PTX helpers (sm_80-level only: cp.async, ldmatrix, mma.sync s8)
// ---------------------------------------------------------------------------
__device__ __forceinline__ uint32_t smem_u32(const void* p) {
    uint32_t a;
    asm("{ .reg .u64 t; cvta.to.shared.u64 t, %1; cvt.u32.u64 %0, t; }"
        : "=r"(a) : "l"(p));
    return a;
}

#define CP16(dst, src) \
    asm volatile("cp.async.cg.shared.global [%0], [%1], 16;" \
                 :: "r"(dst), "l"(src) : "memory")

#define LDSM4(r0, r1, r2, r3, addr) \
    asm volatile("ldmatrix.sync.aligned.m8n8.x4.shared.b16 {%0,%1,%2,%3}, [%4];" \
                 : "=r"(r0), "=r"(r1), "=r"(r2), "=r"(r3) : "r"(addr))

#define MMA_S8(d, a, b) \
    asm volatile("mma.sync.aligned.m16n8k32.row.col.s32.s8.s8.s32 " \
                 "{%0,%1,%2,%3}, {%4,%5,%6,%7}, {%8,%9}, {%0,%1,%2,%3};" \
                 : "+r"((d)[0]), "+r"((d)[1]), "+r"((d)[2]), "+r"((d)[3]) \
                 : "r"((a)[0]), "r"((a)[1]), "r"((a)[2]), "r"((a)[3]), \
                   "r"((b)[0]), "r"((b)[1]))

// quantize 4 fp32 -> 4 s8 bytes
__device__ __forceinline__ uint32_t to_s8x4(float4 v) {
    int a = __float2int_rn(fminf(fmaxf(v.x * QS, -127.f), 127.f));
    int b = __float2int_rn(fminf(fmaxf(v.y * QS, -127.f), 127.f));
    int c = __float2int_rn(fminf(fmaxf(v.z * QS, -127.f), 127.f));
    int d = __float2int_rn(fminf(fmaxf(v.w * QS, -127.f), 127.f));
    return (uint32_t)(a & 0xff) | ((uint32_t)(b & 0xff) << 8) |
           ((uint32_t)(c & 0xff) << 16) | ((uint32_t)(d & 0xff) << 24);
}

// sorted ascending top-4 insert
__device__ __forceinline__ void t4_insert(float (&v)[4], int (&ix)[4],
                                          float s, int i) {
    if (s < v[3]) {
        if (s < v[1]) {
            if (s < v[0]) {
                v[3]=v[2]; ix[3]=ix[2]; v[2]=v[1]; ix[2]=ix[1];
                v[1]=v[0]; ix[1]=ix[0]; v[0]=s; ix[0]=i;
            } else {
                v[3]=v[2]; ix[3]=ix[2]; v[2]=v[1]; ix[2]=ix[1];
                v[1]=s; ix[1]=i;
            }
        } else {
            if (s < v[2]) { v[3]=v[2]; ix[3]=ix[2]; v[2]=s; ix[2]=i; }
            else          { v[3]=s; ix[3]=i; }
        }
    }
}

// ---------------------------------------------------------------------------
// Prep kernels: s8 quantization + 0.5||c||^2 (exact + scaled) + loss zero
// ---------------------------------------------------------------------------
__global__ void prep_x(const float* __restrict__ x) {
    int i = blockIdx.x * blockDim.x + threadIdx.x;  // 8192 x 512
    ((uint32_t*)g_x8)[i] = to_s8x4(((const float4*)x)[i]);
}

__global__ void prep_cb(const float* __restrict__ cb) {
    int n = blockIdx.x, t = threadIdx.x;  // 4096 x 128
    float4 v = ((const float4*)(cb + (size_t)n * DIM))[t];
    ((uint32_t*)g_cb8)[(size_t)n * 128 + t] = to_s8x4(v);

    float s = v.x * v.x + v.y * v.y + v.z * v.z + v.w * v.w;
    #pragma unroll
    for (int off = 16; off > 0; off >>= 1)
        s += __shfl_down_sync(0xffffffffu, s, off);
    __shared__ float ws[4];
    if ((t & 31) == 0) ws[t >> 5] = s;
    __syncthreads();
    if (t == 0) {
        float c2 = 0.5f * (ws[0] + ws[1] + ws[2] + ws[3]);
        g_c2[n]  = c2;
        g_c2s[n] = c2 * (QS * QS);
        if (n == 0) g_loss = 0.0;
    }
}

// ---------------------------------------------------------------------------
// Kernel 1: int8 IMMA distance GEMM + fused per-row top-4 candidates.
// Unit = (128 rows) x (2048 codes: half of codebook). 512 units.
// Scaled score(row, code) = QS^2*0.5||c||^2 - dot_int (same argmin ordering).
// A (128 rows x 512 s8) resident in smem; B streamed, 3-stage cp.async ring.
// ---------------------------------------------------------------------------
__global__ __launch_bounds__(NTHR)
void cand_kernel() {
    extern __shared__ char dsm[];
    const uint32_t sraw = smem_u32(dsm);
    const uint32_t sb   = (sraw + 1023u) & ~1023u;
    char* base = dsm + (sb - sraw);
    const uint32_t Ab = sb;
    const uint32_t Bb = sb + A_BYTES;

    const int tid  = threadIdx.x;
    const int lane = tid & 31, wid = tid >> 5;
    const int warpM = wid & 3, warpN = wid >> 2;
    const int half = blockIdx.x & 1;
    const int m0   = (blockIdx.x >> 1) * M_CTA;
    const int ncb0 = half * NHALF;

    // ldmatrix per-thread address constants (rows are 128B, SW within row)
    const uint32_t arow = (uint32_t)((lane & 7) + ((lane & 8) ? 8 : 0));
    const uint32_t asel = (lane & 16) ? 16u : 0u;
    const uint32_t axr  = (arow & 7u) << 4;
    const uint32_t abase0 = (uint32_t)(warpM * 32 + (int)arow) * 128u;
    const uint32_t abase1 = abase0 + 16u * 128u;
    const uint32_t brow = (uint32_t)((lane & 7) + ((lane & 16) ? 8 : 0));
    const uint32_t bsel = (lane & 8) ? 16u : 0u;
    const uint32_t bxr  = (brow & 7u) << 4;
    const uint32_t bstart = (uint32_t)(warpN * 64 + (int)brow) * 128u;

    // ---- prologue: stage A fully (group 0), B it=0 (g1), B it=1 (g2) ------
    {
        #pragma unroll
        for (int j = 0; j < 16; j++) {
            int e = tid + j * 256;            // 4096 16B segs
            int ch = e >> 10, rem = e & 1023, row = rem >> 3, seg = rem & 7;
            const uint8_t* src = g_x8 + (size_t)(m0 + row) * DIM + ch * BKB + seg * 16;
            uint32_t dst = Ab + (uint32_t)ch * 16384u + (uint32_t)row * 128u +
                           (((uint32_t)seg * 16u) ^ (((uint32_t)row & 7u) << 4));
            CP16(dst, src);
        }
        asm volatile("cp.async.commit_group;" ::: "memory");
        #pragma unroll
        for (int pre = 0; pre < 2; pre++) {
            int nt2 = pre >> 2, kc2 = pre & 3, s2 = pre % 3;
            #pragma unroll
            for (int j = 0; j < 4; j++) {
                int e = tid + j * 256;
                int row = e >> 3, seg = e & 7;
                const uint8_t* src =
                    g_cb8 + (size_t)(ncb0 + nt2 * N_TILE + row) * DIM + kc2 * BKB + seg * 16;
                uint32_t dst = Bb + (uint32_t)s2 * BSTAGE + (uint32_t)row * 128u +
                               (((uint32_t)seg * 16u) ^ (((uint32_t)row & 7u) << 4));
                CP16(dst, src);
            }
            asm volatile("cp.async.commit_group;" ::: "memory");
        }
    }

    int acc[2][8][4];
    #pragma unroll
    for (int mt = 0; mt < 2; mt++)
        #pragma unroll
        for (int p = 0; p < 8; p++)
            #pragma unroll
            for (int c = 0; c < 4; c++) acc[mt][p][c] = 0;

    float t4v[4][4];
    int   t4i[4][4];
    #pragma unroll
    for (int r = 0; r < 4; r++)
        #pragma unroll
        for (int j = 0; j < 4; j++) { t4v[r][j] = 3.4e38f; t4i[r][j] = 0; }

    // ---- main loop ---------------------------------------------------------
    for (int it = 0; it < ITERS; it++) {
        const int nt = it >> 2, kc = it & 3, s = it % 3;
        asm volatile("cp.async.wait_group 1;" ::: "memory");
        __syncthreads();

        // prefetch B for it+2
        const int it2 = it + 2;
        if (it2 < ITERS) {
            const int nt2 = it2 >> 2, kc2 = it2 & 3, s2 = it2 % 3;
            #pragma unroll
            for (int j = 0; j < 4; j++) {
                int e = tid + j * 256;
                int row = e >> 3, seg = e & 7;
                const uint8_t* src =
                    g_cb8 + (size_t)(ncb0 + nt2 * N_TILE + row) * DIM + kc2 * BKB + seg * 16;
                uint32_t dst = Bb + (uint32_t)s2 * BSTAGE + (uint32_t)row * 128u +
                               (((uint32_t)seg * 16u) ^ (((uint32_t)row & 7u) << 4));
                CP16(dst, src);
            }
        }
        asm volatile("cp.async.commit_group;" ::: "memory");

        // compute this 128B k-chunk: 4 k32 steps
        const uint32_t Achunk = Ab + (uint32_t)kc * 16384u;
        const uint32_t Bs     = Bb + (uint32_t)s * BSTAGE;
        #pragma unroll
        for (int ks = 0; ks < 4; ks++) {
            const uint32_t koA = (((uint32_t)(ks * 32)) + asel) ^ axr;
            uint32_t a0[4], a1[4];
            LDSM4(a0[0], a0[1], a0[2], a0[3], Achunk + abase0 + koA);
            LDSM4(a1[0], a1[1], a1[2], a1[3], Achunk + abase1 + koA);
            const uint32_t koB = (((uint32_t)(ks * 32)) + bsel) ^ bxr;
            uint32_t bb[8][2];
            #pragma unroll
            for (int p = 0; p < 4; p++) {
                uint32_t r0, r1, r2, r3;
                LDSM4(r0, r1, r2, r3, Bs + bstart + (uint32_t)p * 2048u + koB);
                bb[2 * p][0] = r0; bb[2 * p][1] = r1;
                bb[2 * p + 1][0] = r2; bb[2 * p + 1][1] = r3;
            }
            #pragma unroll
            for (int p = 0; p < 8; p++) {
                MMA_S8(acc[0][p], a0, bb[p]);
                MMA_S8(acc[1][p], a1, bb[p]);
            }
        }

        // fold finished code tile into running top-4, reset accumulators
        if (kc == CHUNKS - 1) {
            #pragma unroll
            for (int mt = 0; mt < 2; mt++) {
                #pragma unroll
                for (int p = 0; p < 8; p++) {
                    const int ng = ncb0 + nt * N_TILE + warpN * 64 + p * 8 + 2 * (lane & 3);
                    const float2 c2 = __ldg((const float2*)(g_c2s + ng));
                    t4_insert(t4v[mt * 2 + 0], t4i[mt * 2 + 0], c2.x - (float)acc[mt][p][0], ng);
                    t4_insert(t4v[mt * 2 + 0], t4i[mt * 2 + 0], c2.y - (float)acc[mt][p][1], ng + 1);
                    t4_insert(t4v[mt * 2 + 1], t4i[mt * 2 + 1], c2.x - (float)acc[mt][p][2], ng);
                    t4_insert(t4v[mt * 2 + 1], t4i[mt * 2 + 1], c2.y - (float)acc[mt][p][3], ng + 1);
                    acc[mt][p][0] = 0; acc[mt][p][1] = 0;
                    acc[mt][p][2] = 0; acc[mt][p][3] = 0;
                }
            }
        }
    }

    // ---- merge: quad (shfl) -> cross-warpN (smem) --------------------------
    #pragma unroll
    for (int rs = 0; rs < 4; rs++) {
        #pragma unroll
        for (int delta = 1; delta <= 2; delta <<= 1) {
            float ov[4]; int oi[4];
            #pragma unroll
            for (int j = 0; j < 4; j++) {
                ov[j] = __shfl_xor_sync(0xffffffffu, t4v[rs][j], delta);
                oi[j] = __shfl_xor_sync(0xffffffffu, t4i[rs][j], delta);
            }
            #pragma unroll
            for (int j = 0; j < 4; j++) t4_insert(t4v[rs], t4i[rs], ov[j], oi[j]);
        }
    }

    __syncthreads();
    float* mv = (float*)(base + MERGE_OFF);
    int*   mi = (int*)(base + MERGE_OFF + 4096);
    if ((lane & 3) == 0) {
        #pragma unroll
        for (int rs = 0; rs < 4; rs++) {
            int row_local = warpM * 32 + (rs >> 1) * 16 + ((rs & 1) << 3) + (lane >> 2);
            int idx = (warpN * 128 + row_local) * 4;
            #pragma unroll
            for (int j = 0; j < 4; j++) { mv[idx + j] = t4v[rs][j]; mi[idx + j] = t4i[rs][j]; }
        }
    }
    __syncthreads();
    if (tid < 128) {
        float v[4]; int ix[4];
        #pragma unroll
        for (int j = 0; j < 4; j++) { v[j] = mv[tid * 4 + j]; ix[j] = mi[tid * 4 + j]; }
        #pragma unroll
        for (int j = 0; j < 4; j++)
            t4_insert(v, ix, mv[(128 + tid) * 4 + j], mi[(128 + tid) * 4 + j]);
        #pragma unroll
        for (int j = 0; j < 4; j++)
            g_cand[(size_t)(m0 + tid) * 8 + half * 4 + j] = ix[j];
    }
}

// ---------------------------------------------------------------------------
// Kernel 2: exact fp32 rescore of 8 candidates, argmin (tie -> lower index),
// gather nearest, accumulate loss. out_near base only 8B aligned -> float2.
// ---------------------------------------------------------------------------
__global__ void rescore_gather_kernel(const float* __restrict__ x,
                                      const float* __restrict__ cb,
                                      float* __restrict__ out_enc,
                                      float* __restrict__ out_near) {
    const int row = blockIdx.x;   // 32768
    const int t   = threadIdx.x;  // 128
    __shared__ float sdot[4][8];
    __shared__ int   s_enc;
    __shared__ float ws[4];

    int cand[8];
    #pragma unroll
    for (int j = 0; j < 8; j++) cand[j] = g_cand[(size_t)row * 8 + j];

    const float4 xv = ((const float4*)(x + (size_t)row * DIM))[t];
    #pragma unroll
    for (int j = 0; j < 8; j++) {
        const float4 cv = ((const float4*)(cb + (size_t)cand[j] * DIM))[t];
        float p = xv.x * cv.x + xv.y * cv.y + xv.z * cv.z + xv.w * cv.w;
        #pragma unroll
        for (int off = 16; off > 0; off >>= 1)
            p += __shfl_down_sync(0xffffffffu, p, off);
        if ((t & 31) == 0) sdot[t >> 5][j] = p;
    }
    __syncthreads();
    if (t == 0) {
        float bs = 3.4e38f; int bi = 0x7fffffff;
        #pragma unroll
        for (int j = 0; j < 8; j++) {
            float dot = sdot[0][j] + sdot[1][j] + sdot[2][j] + sdot[3][j];
            float s = g_c2[cand[j]] - dot;
            if (s < bs || (s == bs && cand[j] < bi)) { bs = s; bi = cand[j]; }
        }
        s_enc = bi;
        out_enc[row] = (float)bi;
    }
    __syncthreads();
    const int enc = s_enc;

    const float4 c = ((const float4*)(cb + (size_t)enc * DIM))[t];
    float2* orow = (float2*)(out_near + (size_t)row * DIM);
    orow[2 * t]     = make_float2(c.x, c.y);
    orow[2 * t + 1] = make_float2(c.z, c.w);
    float dx = xv.x - c.x, dy = xv.y - c.y, dz = xv.z - c.z, dw = xv.w - c.w;
    float s = dx * dx + dy * dy + dz * dz + dw * dw;
    #pragma unroll
    for (int off = 16; off > 0; off >>= 1)
        s += __shfl_down_sync(0xffffffffu, s, off);
    if ((t & 31) == 0) ws[t >> 5] = s;
    __syncthreads();
    if (t == 0) {
        double tot = (double)ws[0] + (double)ws[1] + (double)ws[2] + (double)ws[3];
        atomicAdd(&g_loss, tot);
    }
}

__global__ void finalize_kernel(float* __restrict__ out_losses) {
    double mean = g_loss / ((double)N_ROWS * (double)DIM);
    out_losses[0] = (float)mean;
    out_losses[1] = (float)mean;
}

// ---------------------------------------------------------------------------
// Output layout (float32): [0,32768) encoding; [32768,32770) losses;
// [32770, ...) nearest (base only 8B aligned).
// ---------------------------------------------------------------------------
extern "C" void kernel_launch(void* const* d_in, const int* in_sizes, int n_in,
                              void* d_out, int out_size) {
    const float* x  = (const float*)d_in[0];
    const float* cb = (const float*)d_in[1];
    if (n_in >= 2 && in_sizes[0] == KCODES * DIM && in_sizes[1] == N_ROWS * DIM) {
        const float* tmp = x; x = cb; cb = tmp;
    }

    float* out        = (float*)d_out;
    float* out_enc    = out;
    float* out_losses = out + N_ROWS;
    float* out_near   = out + N_ROWS + 2;

    static int smem_set = 0;
    if (!smem_set) {
        cudaFuncSetAttribute(cand_kernel,
                             cudaFuncAttributeMaxDynamicSharedMemorySize, DYN_SMEM);
        smem_set = 1;
    }

    prep_x<<<8192, 512>>>(x);
    prep_cb<<<KCODES, 128>>>(cb);
    cand_kernel<<<GRID, NTHR, DYN_SMEM>>>();
    rescore_gather_kernel<<<N_ROWS, 128>>>(x, cb, out_enc, out_near);
    finalize_kernel<<<1, 1>>>(out_losses);
}

// round 10
// speedup vs baseline: 1.9365x; 1.3588x over previous
#include <cuda_runtime.h>
#include <cuda_bf16.h>
#include <cstdint>

// Problem constants (fixed: B=8, S=4096, D=512, CD=4096)
#define N_ROWS 32768
#define DIM    512
#define KCODES 4096

// cand kernel tiling (int8, single wave: 128 CTAs x 512 threads)
#define M_CTA   256                 // rows per CTA
#define N_TILE  128                 // codes per B stage
#define BKB     128                 // int8 K elems per chunk (=128B rows)
#define CHUNKS  (DIM / BKB)         // 4
#define NT      (KCODES / N_TILE)   // 32
#define ITERS   (NT * CHUNKS)       // 128
#define GRID    (N_ROWS / M_CTA)    // 128
#define NTHR    512

#define QS 23.0f                    // int8 quant scale

// smem: [align 1KB][A 128KB][B 3x16KB]; merge aliases B after compute
#define A_BYTES   (M_CTA * DIM)              // 131072
#define BSTAGE    (N_TILE * BKB)             // 16384
#define DYN_SMEM  (1024 + A_BYTES + 3 * BSTAGE)  // 181248

// Scratch (device globals; no allocation allowed)
__device__ __align__(16) float  g_c2[KCODES];    // exact 0.5*||c||^2 (rescore)
__device__ __align__(16) float  g_c2s[KCODES];   // 0.5*||c||^2 * QS^2 (filter)
__device__ int    g_cand[N_ROWS * 8];            // top-4 per code-half, 8/row
__device__ double g_loss;
__device__ __align__(16) uint8_t g_cb8[KCODES * DIM];  // 2MB s8

// ---------------------------------------------------------------------------
// PTX helpers (sm_80-level only: cp.async, ldmatrix, mma.sync s8)
// ---------------------------------------------------------------------------
__device__ __forceinline__ uint32_t smem_u32(const void* p) {
    uint32_t a;
    asm("{ .reg .u64 t; cvta.to.shared.u64 t, %1; cvt.u32.u64 %0, t; }"
        : "=r"(a) : "l"(p));
    return a;
}

#define SW128(off) ((off) ^ (((off) >> 3) & 0x70))

#define CP16(dst, src) \
    asm volatile("cp.async.cg.shared.global [%0], [%1], 16;" \
                 :: "r"(dst), "l"(src) : "memory")

#define LDSM4(r0, r1, r2, r3, addr) \
    asm volatile("ldmatrix.sync.aligned.m8n8.x4.shared.b16 {%0,%1,%2,%3}, [%4];" \
                 : "=r"(r0), "=r"(r1), "=r"(r2), "=r"(r3) : "r"(addr))

#define MMA_S8(d, a, b) \
    asm volatile("mma.sync.aligned.m16n8k32.row.col.s32.s8.s8.s32 " \
                 "{%0,%1,%2,%3}, {%4,%5,%6,%7}, {%8,%9}, {%0,%1,%2,%3};" \
                 : "+r"((d)[0]), "+r"((d)[1]), "+r"((d)[2]), "+r"((d)[3]) \
                 : "r"((a)[0]), "r"((a)[1]), "r"((a)[2]), "r"((a)[3]), \
                   "r"((b)[0]), "r"((b)[1]))

// quantize 4 fp32 -> 4 s8 bytes
__device__ __forceinline__ uint32_t to_s8x4(float4 v) {
    int a = __float2int_rn(fminf(fmaxf(v.x * QS, -127.f), 127.f));
    int b = __float2int_rn(fminf(fmaxf(v.y * QS, -127.f), 127.f));
    int c = __float2int_rn(fminf(fmaxf(v.z * QS, -127.f), 127.f));
    int d = __float2int_rn(fminf(fmaxf(v.w * QS, -127.f), 127.f));
    return (uint32_t)(a & 0xff) | ((uint32_t)(b & 0xff) << 8) |
           ((uint32_t)(c & 0xff) << 16) | ((uint32_t)(d & 0xff) << 24);
}

// sorted ascending top-4 insert
__device__ __forceinline__ void t4_insert(float (&v)[4], int (&ix)[4],
                                          float s, int i) {
    if (s < v[3]) {
        if (s < v[1]) {
            if (s < v[0]) {
                v[3]=v[2]; ix[3]=ix[2]; v[2]=v[1]; ix[2]=ix[1];
                v[1]=v[0]; ix[1]=ix[0]; v[0]=s; ix[0]=i;
            } else {
                v[3]=v[2]; ix[3]=ix[2]; v[2]=v[1]; ix[2]=ix[1];
                v[1]=s; ix[1]=i;
            }
        } else {
            if (s < v[2]) { v[3]=v[2]; ix[3]=ix[2]; v[2]=s; ix[2]=i; }
            else          { v[3]=s; ix[3]=i; }
        }
    }
}

// ---------------------------------------------------------------------------
// Prep: codebook s8 quantization + 0.5||c||^2 (exact + scaled) + loss zero
// ---------------------------------------------------------------------------
__global__ void prep_cb(const float* __restrict__ cb) {
    int n = blockIdx.x, t = threadIdx.x;  // 4096 x 128
    float4 v = ((const float4*)(cb + (size_t)n * DIM))[t];
    ((uint32_t*)g_cb8)[(size_t)n * 128 + t] = to_s8x4(v);

    float s = v.x * v.x + v.y * v.y + v.z * v.z + v.w * v.w;
    #pragma unroll
    for (int off = 16; off > 0; off >>= 1)
        s += __shfl_down_sync(0xffffffffu, s, off);
    __shared__ float ws[4];
    if ((t & 31) == 0) ws[t >> 5] = s;
    __syncthreads();
    if (t == 0) {
        float c2 = 0.5f * (ws[0] + ws[1] + ws[2] + ws[3]);
        g_c2[n]  = c2;
        g_c2s[n] = c2 * (QS * QS);
        if (n == 0) g_loss = 0.0;
    }
}

// ---------------------------------------------------------------------------
// Kernel 1: int8 IMMA distance GEMM + fused per-row candidates.
// CTA = 256 rows x full 4096 codes, 512 threads (16 warps, 32(M)x64(N) tiles).
// Each (row, warpN) pair scans a disjoint 2048-code half; we keep top-4 PER
// HALF and output the union (8 candidates/row) -- same precision contract as
// the R8 split kernel that verified exactly.
// ---------------------------------------------------------------------------
__global__ __launch_bounds__(NTHR, 1)
void cand_kernel(const float* __restrict__ x) {
    extern __shared__ char dsm[];
    const uint32_t sraw = smem_u32(dsm);
    const uint32_t sb   = (sraw + 1023u) & ~1023u;
    const uint32_t Ab = sb;
    const uint32_t Bb = sb + A_BYTES;

    const int tid  = threadIdx.x;
    const int lane = tid & 31, wid = tid >> 5;   // 16 warps
    const int warpM = wid & 7, warpN = wid >> 3; // 8 (M) x 2 (N)
    const int m0 = blockIdx.x * M_CTA;

    // ldmatrix per-thread address constants (rows are 128B, SW within row)
    const uint32_t arow = (uint32_t)((lane & 7) + ((lane & 8) ? 8 : 0));
    const uint32_t asel = (lane & 16) ? 16u : 0u;
    const uint32_t axr  = (arow & 7u) << 4;
    const uint32_t abase0 = (uint32_t)(warpM * 32 + (int)arow) * 128u;
    const uint32_t abase1 = abase0 + 16u * 128u;
    const uint32_t brow = (uint32_t)((lane & 7) + ((lane & 16) ? 8 : 0));
    const uint32_t bsel = (lane & 8) ? 16u : 0u;
    const uint32_t bxr  = (brow & 7u) << 4;
    const uint32_t bstart = (uint32_t)(warpN * 64 + (int)brow) * 128u;

    // ---- prologue: B it0/it1 via cp.async, then A quantize into smem -------
    #pragma unroll
    for (int pre = 0; pre < 2; pre++) {
        const int kc2 = pre & 3;  // nt=0
        #pragma unroll
        for (int j = 0; j < 2; j++) {
            int e = tid + j * 512;           // 1024 16B segs
            int row = e >> 3, seg = e & 7;
            const uint8_t* src = g_cb8 + (size_t)row * DIM + kc2 * BKB + seg * 16;
            uint32_t dst = Bb + (uint32_t)pre * BSTAGE + (uint32_t)row * 128u +
                           (((uint32_t)seg * 16u) ^ (((uint32_t)row & 7u) << 4));
            CP16(dst, src);
        }
        asm volatile("cp.async.commit_group;" ::: "memory");
    }
    // A: 256 rows x 512 fp32 -> s8 swizzled smem (64 float4 per thread)
    {
        const float4* xv4 = (const float4*)(x + (size_t)m0 * DIM);
        #pragma unroll
        for (int i = 0; i < 64; i++) {
            int f   = tid + i * 512;          // 0..32767
            int row = f >> 7, q = f & 127;    // q: float4 within row
            int ch  = q >> 5, cs = q & 31;    // chunk, 4B slot in chunk
            uint32_t pk = to_s8x4(xv4[f]);
            uint32_t off = (uint32_t)row * 128u + (uint32_t)cs * 4u;
            uint32_t dst = Ab + (uint32_t)ch * 32768u + SW128(off);
            asm volatile("st.shared.u32 [%0], %1;" :: "r"(dst), "r"(pk) : "memory");
        }
    }
    __syncthreads();

    int acc[2][8][4];
    #pragma unroll
    for (int mt = 0; mt < 2; mt++)
        #pragma unroll
        for (int p = 0; p < 8; p++)
            #pragma unroll
            for (int c = 0; c < 4; c++) acc[mt][p][c] = 0;

    float t4v[4][4];
    int   t4i[4][4];
    #pragma unroll
    for (int r = 0; r < 4; r++)
        #pragma unroll
        for (int j = 0; j < 4; j++) { t4v[r][j] = 3.4e38f; t4i[r][j] = 0; }

    // ---- main loop ---------------------------------------------------------
    for (int it = 0; it < ITERS; it++) {
        const int nt = it >> 2, kc = it & 3, s = it % 3;
        asm volatile("cp.async.wait_group 1;" ::: "memory");
        __syncthreads();

        // prefetch B for it+2
        const int it2 = it + 2;
        if (it2 < ITERS) {
            const int nt2 = it2 >> 2, kc2 = it2 & 3, s2 = it2 % 3;
            #pragma unroll
            for (int j = 0; j < 2; j++) {
                int e = tid + j * 512;
                int row = e >> 3, seg = e & 7;
                const uint8_t* src =
                    g_cb8 + (size_t)(nt2 * N_TILE + row) * DIM + kc2 * BKB + seg * 16;
                uint32_t dst = Bb + (uint32_t)s2 * BSTAGE + (uint32_t)row * 128u +
                               (((uint32_t)seg * 16u) ^ (((uint32_t)row & 7u) << 4));
                CP16(dst, src);
            }
        }
        asm volatile("cp.async.commit_group;" ::: "memory");

        // compute this 128B k-chunk: 4 k32 steps
        const uint32_t Achunk = Ab + (uint32_t)kc * 32768u;
        const uint32_t Bs     = Bb + (uint32_t)s * BSTAGE;
        #pragma unroll
        for (int ks = 0; ks < 4; ks++) {
            const uint32_t koA = (((uint32_t)(ks * 32)) + asel) ^ axr;
            uint32_t a0[4], a1[4];
            LDSM4(a0[0], a0[1], a0[2], a0[3], Achunk + abase0 + koA);
            LDSM4(a1[0], a1[1], a1[2], a1[3], Achunk + abase1 + koA);
            const uint32_t koB = (((uint32_t)(ks * 32)) + bsel) ^ bxr;
            uint32_t bb[8][2];
            #pragma unroll
            for (int p = 0; p < 4; p++) {
                uint32_t r0, r1, r2, r3;
                LDSM4(r0, r1, r2, r3, Bs + bstart + (uint32_t)p * 2048u + koB);
                bb[2 * p][0] = r0; bb[2 * p][1] = r1;
                bb[2 * p + 1][0] = r2; bb[2 * p + 1][1] = r3;
            }
            #pragma unroll
            for (int p = 0; p < 8; p++) {
                MMA_S8(acc[0][p], a0, bb[p]);
                MMA_S8(acc[1][p], a1, bb[p]);
            }
        }

        // fold finished code tile into running top-4, reset accumulators
        if (kc == CHUNKS - 1) {
            #pragma unroll
            for (int mt = 0; mt < 2; mt++) {
                #pragma unroll
                for (int p = 0; p < 8; p++) {
                    const int ng = nt * N_TILE + warpN * 64 + p * 8 + 2 * (lane & 3);
                    const float2 c2 = __ldg((const float2*)(g_c2s + ng));
                    t4_insert(t4v[mt * 2 + 0], t4i[mt * 2 + 0], c2.x - (float)acc[mt][p][0], ng);
                    t4_insert(t4v[mt * 2 + 0], t4i[mt * 2 + 0], c2.y - (float)acc[mt][p][1], ng + 1);
                    t4_insert(t4v[mt * 2 + 1], t4i[mt * 2 + 1], c2.x - (float)acc[mt][p][2], ng);
                    t4_insert(t4v[mt * 2 + 1], t4i[mt * 2 + 1], c2.y - (float)acc[mt][p][3], ng + 1);
                    acc[mt][p][0] = 0; acc[mt][p][1] = 0;
                    acc[mt][p][2] = 0; acc[mt][p][3] = 0;
                }
            }
        }
    }

    // ---- merge: quad (shfl) -> per-(row, warpN-half) top-4 -----------------
    #pragma unroll
    for (int rs = 0; rs < 4; rs++) {
        #pragma unroll
        for (int delta = 1; delta <= 2; delta <<= 1) {
            float ov[4]; int oi[4];
            #pragma unroll
            for (int j = 0; j < 4; j++) {
                ov[j] = __shfl_xor_sync(0xffffffffu, t4v[rs][j], delta);
                oi[j] = __shfl_xor_sync(0xffffffffu, t4i[rs][j], delta);
            }
            #pragma unroll
            for (int j = 0; j < 4; j++) t4_insert(t4v[rs], t4i[rs], ov[j], oi[j]);
        }
    }

    __syncthreads();  // all compute done: safe to alias B-stage smem
    int* mi = (int*)(dsm + (Bb - sraw));   // 2 halves x 256 rows x 4 ints
    if ((lane & 3) == 0) {
        #pragma unroll
        for (int rs = 0; rs < 4; rs++) {
            int row_local = warpM * 32 + (rs >> 1) * 16 + ((rs & 1) << 3) + (lane >> 2);
            int idx = (warpN * 256 + row_local) * 4;
            #pragma unroll
            for (int j = 0; j < 4; j++) mi[idx + j] = t4i[rs][j];
        }
    }
    __syncthreads();
    // union of both halves' top-4 -> 8 candidates per row (no reduction)
    if (tid < 256) {
        #pragma unroll
        for (int j = 0; j < 4; j++) {
            g_cand[(size_t)(m0 + tid) * 8 + j]     = mi[tid * 4 + j];
            g_cand[(size_t)(m0 + tid) * 8 + 4 + j] = mi[(256 + tid) * 4 + j];
        }
    }
}

// ---------------------------------------------------------------------------
// Kernel 2: exact fp32 rescore of 8 candidates, argmin (tie -> lower index),
// gather nearest, accumulate loss. out_near base only 8B aligned -> float2.
// ---------------------------------------------------------------------------
__global__ void rescore_gather_kernel(const float* __restrict__ x,
                                      const float* __restrict__ cb,
                                      float* __restrict__ out_enc,
                                      float* __restrict__ out_near) {
    const int row = blockIdx.x;   // 32768
    const int t   = threadIdx.x;  // 128
    __shared__ float sdot[4][8];
    __shared__ int   s_enc;
    __shared__ float ws[4];

    int cand[8];
    #pragma unroll
    for (int j = 0; j < 8; j++) cand[j] = g_cand[(size_t)row * 8 + j];

    const float4 xv = ((const float4*)(x + (size_t)row * DIM))[t];
    #pragma unroll
    for (int j = 0; j < 8; j++) {
        const float4 cv = ((const float4*)(cb + (size_t)cand[j] * DIM))[t];
        float p = xv.x * cv.x + xv.y * cv.y + xv.z * cv.z + xv.w * cv.w;
        #pragma unroll
        for (int off = 16; off > 0; off >>= 1)
            p += __shfl_down_sync(0xffffffffu, p, off);
        if ((t & 31) == 0) sdot[t >> 5][j] = p;
    }
    __syncthreads();
    if (t == 0) {
        float bs = 3.4e38f; int bi = 0x7fffffff;
        #pragma unroll
        for (int j = 0; j < 8; j++) {
            float dot = sdot[0][j] + sdot[1][j] + sdot[2][j] + sdot[3][j];
            float s = g_c2[cand[j]] - dot;
            if (s < bs || (s == bs && cand[j] < bi)) { bs = s; bi = cand[j]; }
        }
        s_enc = bi;
        out_enc[row] = (float)bi;
    }
    __syncthreads();
    const int enc = s_enc;

    const float4 c = ((const float4*)(cb + (size_t)enc * DIM))[t];
    float2* orow = (float2*)(out_near + (size_t)row * DIM);
    orow[2 * t]     = make_float2(c.x, c.y);
    orow[2 * t + 1] = make_float2(c.z, c.w);
    float dx = xv.x - c.x, dy = xv.y - c.y, dz = xv.z - c.z, dw = xv.w - c.w;
    float s = dx * dx + dy * dy + dz * dz + dw * dw;
    #pragma unroll
    for (int off = 16; off > 0; off >>= 1)
        s += __shfl_down_sync(0xffffffffu, s, off);
    if ((t & 31) == 0) ws[t >> 5] = s;
    __syncthreads();
    if (t == 0) {
        double tot = (double)ws[0] + (double)ws[1] + (double)ws[2] + (double)ws[3];
        atomicAdd(&g_loss, tot);
    }
}

__global__ void finalize_kernel(float* __restrict__ out_losses) {
    double mean = g_loss / ((double)N_ROWS * (double)DIM);
    out_losses[0] = (float)mean;
    out_losses[1] = (float)mean;
}

// ---------------------------------------------------------------------------
// Output layout (float32): [0,32768) encoding; [32768,32770) losses;
// [32770, ...) nearest (base only 8B aligned).
// ---------------------------------------------------------------------------
extern "C" void kernel_launch(void* const* d_in, const int* in_sizes, int n_in,
                              void* d_out, int out_size) {
    const float* x  = (const float*)d_in[0];
    const float* cb = (const float*)d_in[1];
    if (n_in >= 2 && in_sizes[0] == KCODES * DIM && in_sizes[1] == N_ROWS * DIM) {
        const float* tmp = x; x = cb; cb = tmp;
    }

    float* out        = (float*)d_out;
    float* out_enc    = out;
    float* out_losses = out + N_ROWS;
    float* out_near   = out + N_ROWS + 2;

    static int smem_set = 0;
    if (!smem_set) {
        cudaFuncSetAttribute(cand_kernel,
                             cudaFuncAttributeMaxDynamicSharedMemorySize, DYN_SMEM);
        smem_set = 1;
    }

    prep_cb<<<KCODES, 128>>>(cb);
    cand_kernel<<<GRID, NTHR, DYN_SMEM>>>(x);
    rescore_gather_kernel<<<N_ROWS, 128>>>(x, cb, out_enc, out_near);
    finalize_kernel<<<1, 1>>>(out_losses);
}

// round 11
// speedup vs baseline: 1.9682x; 1.0164x over previous
#include <cuda_runtime.h>
#include <cuda_bf16.h>
#include <cstdint>

// Problem constants (fixed: B=8, S=4096, D=512, CD=4096)
#define N_ROWS 32768
#define DIM    512
#define KCODES 4096

// cand kernel tiling (int8, single wave: 128 CTAs x 512 threads)
#define M_CTA   256                 // rows per CTA
#define N_TILE  128                 // codes per B stage
#define BKB     128                 // int8 K elems per chunk (=128B rows)
#define CHUNKS  (DIM / BKB)         // 4
#define NT      (KCODES / N_TILE)   // 32
#define ITERS   (NT * CHUNKS)       // 128
#define GRID    (N_ROWS / M_CTA)    // 128
#define NTHR    512

#define QS 23.0f                    // int8 quant scale
#define DELTA 5000.0f               // rescore margin, scaled units (~17 sigma)

// smem: [align 1KB][A 128KB][B 3x16KB]; merge aliases B after compute
#define A_BYTES   (M_CTA * DIM)              // 131072
#define BSTAGE    (N_TILE * BKB)             // 16384
#define DYN_SMEM  (1024 + A_BYTES + 3 * BSTAGE)  // 181248

// Scratch (device globals; no allocation allowed)
__device__ __align__(16) float  g_c2[KCODES];    // exact 0.5*||c||^2 (rescore)
__device__ __align__(16) float  g_c2s[KCODES];   // 0.5*||c||^2 * QS^2 (filter)
__device__ int    g_cand[N_ROWS * 8];            // top-4 per code-half, 8/row
__device__ float  g_csc[N_ROWS * 8];             // their scaled scores
__device__ double g_loss;
__device__ __align__(16) uint8_t g_cb8[KCODES * DIM];  // 2MB s8

// ---------------------------------------------------------------------------
// PTX helpers (sm_80-level only: cp.async, ldmatrix, mma.sync s8)
// ---------------------------------------------------------------------------
__device__ __forceinline__ uint32_t smem_u32(const void* p) {
    uint32_t a;
    asm("{ .reg .u64 t; cvta.to.shared.u64 t, %1; cvt.u32.u64 %0, t; }"
        : "=r"(a) : "l"(p));
    return a;
}

#define SW128(off) ((off) ^ (((off) >> 3) & 0x70))

#define CP16(dst, src) \
    asm volatile("cp.async.cg.shared.global [%0], [%1], 16;" \
                 :: "r"(dst), "l"(src) : "memory")

#define LDSM4(r0, r1, r2, r3, addr) \
    asm volatile("ldmatrix.sync.aligned.m8n8.x4.shared.b16 {%0,%1,%2,%3}, [%4];" \
                 : "=r"(r0), "=r"(r1), "=r"(r2), "=r"(r3) : "r"(addr))

#define MMA_S8(d, a, b) \
    asm volatile("mma.sync.aligned.m16n8k32.row.col.s32.s8.s8.s32 " \
                 "{%0,%1,%2,%3}, {%4,%5,%6,%7}, {%8,%9}, {%0,%1,%2,%3};" \
                 : "+r"((d)[0]), "+r"((d)[1]), "+r"((d)[2]), "+r"((d)[3]) \
                 : "r"((a)[0]), "r"((a)[1]), "r"((a)[2]), "r"((a)[3]), \
                   "r"((b)[0]), "r"((b)[1]))

// quantize 4 fp32 -> 4 s8 bytes
__device__ __forceinline__ uint32_t to_s8x4(float4 v) {
    int a = __float2int_rn(fminf(fmaxf(v.x * QS, -127.f), 127.f));
    int b = __float2int_rn(fminf(fmaxf(v.y * QS, -127.f), 127.f));
    int c = __float2int_rn(fminf(fmaxf(v.z * QS, -127.f), 127.f));
    int d = __float2int_rn(fminf(fmaxf(v.w * QS, -127.f), 127.f));
    return (uint32_t)(a & 0xff) | ((uint32_t)(b & 0xff) << 8) |
           ((uint32_t)(c & 0xff) << 16) | ((uint32_t)(d & 0xff) << 24);
}

// sorted ascending top-4 insert
__device__ __forceinline__ void t4_insert(float (&v)[4], int (&ix)[4],
                                          float s, int i) {
    if (s < v[3]) {
        if (s < v[1]) {
            if (s < v[0]) {
                v[3]=v[2]; ix[3]=ix[2]; v[2]=v[1]; ix[2]=ix[1];
                v[1]=v[0]; ix[1]=ix[0]; v[0]=s; ix[0]=i;
            } else {
                v[3]=v[2]; ix[3]=ix[2]; v[2]=v[1]; ix[2]=ix[1];
                v[1]=s; ix[1]=i;
            }
        } else {
            if (s < v[2]) { v[3]=v[2]; ix[3]=ix[2]; v[2]=s; ix[2]=i; }
            else          { v[3]=s; ix[3]=i; }
        }
    }
}

// ---------------------------------------------------------------------------
// Prep: codebook s8 quantization + 0.5||c||^2 (exact + scaled) + loss zero
// ---------------------------------------------------------------------------
__global__ void prep_cb(const float* __restrict__ cb) {
    int n = blockIdx.x, t = threadIdx.x;  // 4096 x 128
    float4 v = ((const float4*)(cb + (size_t)n * DIM))[t];
    ((uint32_t*)g_cb8)[(size_t)n * 128 + t] = to_s8x4(v);

    float s = v.x * v.x + v.y * v.y + v.z * v.z + v.w * v.w;
    #pragma unroll
    for (int off = 16; off > 0; off >>= 1)
        s += __shfl_down_sync(0xffffffffu, s, off);
    __shared__ float ws[4];
    if ((t & 31) == 0) ws[t >> 5] = s;
    __syncthreads();
    if (t == 0) {
        float c2 = 0.5f * (ws[0] + ws[1] + ws[2] + ws[3]);
        g_c2[n]  = c2;
        g_c2s[n] = c2 * (QS * QS);
        if (n == 0) g_loss = 0.0;
    }
}

// ---------------------------------------------------------------------------
// Kernel 1: int8 IMMA distance GEMM + fused per-row candidates.
// CTA = 256 rows x full 4096 codes, 512 threads (16 warps, 32(M)x64(N) tiles).
// Each (row, warpN) pair scans a disjoint 2048-code half; we keep top-4 PER
// HALF and output the union (8 candidates/row) with their scaled scores.
// ---------------------------------------------------------------------------
__global__ __launch_bounds__(NTHR, 1)
void cand_kernel(const float* __restrict__ x) {
    extern __shared__ char dsm[];
    const uint32_t sraw = smem_u32(dsm);
    const uint32_t sb   = (sraw + 1023u) & ~1023u;
    const uint32_t Ab = sb;
    const uint32_t Bb = sb + A_BYTES;

    const int tid  = threadIdx.x;
    const int lane = tid & 31, wid = tid >> 5;   // 16 warps
    const int warpM = wid & 7, warpN = wid >> 3; // 8 (M) x 2 (N)
    const int m0 = blockIdx.x * M_CTA;

    // ldmatrix per-thread address constants (rows are 128B, SW within row)
    const uint32_t arow = (uint32_t)((lane & 7) + ((lane & 8) ? 8 : 0));
    const uint32_t asel = (lane & 16) ? 16u : 0u;
    const uint32_t axr  = (arow & 7u) << 4;
    const uint32_t abase0 = (uint32_t)(warpM * 32 + (int)arow) * 128u;
    const uint32_t abase1 = abase0 + 16u * 128u;
    const uint32_t brow = (uint32_t)((lane & 7) + ((lane & 16) ? 8 : 0));
    const uint32_t bsel = (lane & 8) ? 16u : 0u;
    const uint32_t bxr  = (brow & 7u) << 4;
    const uint32_t bstart = (uint32_t)(warpN * 64 + (int)brow) * 128u;

    // ---- prologue: B it0/it1 via cp.async, then A quantize into smem -------
    #pragma unroll
    for (int pre = 0; pre < 2; pre++) {
        const int kc2 = pre & 3;  // nt=0
        #pragma unroll
        for (int j = 0; j < 2; j++) {
            int e = tid + j * 512;           // 1024 16B segs
            int row = e >> 3, seg = e & 7;
            const uint8_t* src = g_cb8 + (size_t)row * DIM + kc2 * BKB + seg * 16;
            uint32_t dst = Bb + (uint32_t)pre * BSTAGE + (uint32_t)row * 128u +
                           (((uint32_t)seg * 16u) ^ (((uint32_t)row & 7u) << 4));
            CP16(dst, src);
        }
        asm volatile("cp.async.commit_group;" ::: "memory");
    }
    // A: 256 rows x 512 fp32 -> s8 swizzled smem (64 float4 per thread)
    {
        const float4* xv4 = (const float4*)(x + (size_t)m0 * DIM);
        #pragma unroll
        for (int i = 0; i < 64; i++) {
            int f   = tid + i * 512;          // 0..32767
            int row = f >> 7, q = f & 127;    // q: float4 within row
            int ch  = q >> 5, cs = q & 31;    // chunk, 4B slot in chunk
            uint32_t pk = to_s8x4(xv4[f]);
            uint32_t off = (uint32_t)row * 128u + (uint32_t)cs * 4u;
            uint32_t dst = Ab + (uint32_t)ch * 32768u + SW128(off);
            asm volatile("st.shared.u32 [%0], %1;" :: "r"(dst), "r"(pk) : "memory");
        }
    }
    __syncthreads();

    int acc[2][8][4];
    #pragma unroll
    for (int mt = 0; mt < 2; mt++)
        #pragma unroll
        for (int p = 0; p < 8; p++)
            #pragma unroll
            for (int c = 0; c < 4; c++) acc[mt][p][c] = 0;

    float t4v[4][4];
    int   t4i[4][4];
    #pragma unroll
    for (int r = 0; r < 4; r++)
        #pragma unroll
        for (int j = 0; j < 4; j++) { t4v[r][j] = 3.4e38f; t4i[r][j] = 0; }

    // ---- main loop ---------------------------------------------------------
    for (int it = 0; it < ITERS; it++) {
        const int nt = it >> 2, kc = it & 3, s = it % 3;
        asm volatile("cp.async.wait_group 1;" ::: "memory");
        __syncthreads();

        // prefetch B for it+2
        const int it2 = it + 2;
        if (it2 < ITERS) {
            const int nt2 = it2 >> 2, kc2 = it2 & 3, s2 = it2 % 3;
            #pragma unroll
            for (int j = 0; j < 2; j++) {
                int e = tid + j * 512;
                int row = e >> 3, seg = e & 7;
                const uint8_t* src =
                    g_cb8 + (size_t)(nt2 * N_TILE + row) * DIM + kc2 * BKB + seg * 16;
                uint32_t dst = Bb + (uint32_t)s2 * BSTAGE + (uint32_t)row * 128u +
                               (((uint32_t)seg * 16u) ^ (((uint32_t)row & 7u) << 4));
                CP16(dst, src);
            }
        }
        asm volatile("cp.async.commit_group;" ::: "memory");

        // compute this 128B k-chunk: 4 k32 steps
        const uint32_t Achunk = Ab + (uint32_t)kc * 32768u;
        const uint32_t Bs     = Bb + (uint32_t)s * BSTAGE;
        #pragma unroll
        for (int ks = 0; ks < 4; ks++) {
            const uint32_t koA = (((uint32_t)(ks * 32)) + asel) ^ axr;
            uint32_t a0[4], a1[4];
            LDSM4(a0[0], a0[1], a0[2], a0[3], Achunk + abase0 + koA);
            LDSM4(a1[0], a1[1], a1[2], a1[3], Achunk + abase1 + koA);
            const uint32_t koB = (((uint32_t)(ks * 32)) + bsel) ^ bxr;
            uint32_t bb[8][2];
            #pragma unroll
            for (int p = 0; p < 4; p++) {
                uint32_t r0, r1, r2, r3;
                LDSM4(r0, r1, r2, r3, Bs + bstart + (uint32_t)p * 2048u + koB);
                bb[2 * p][0] = r0; bb[2 * p][1] = r1;
                bb[2 * p + 1][0] = r2; bb[2 * p + 1][1] = r3;
            }
            #pragma unroll
            for (int p = 0; p < 8; p++) {
                MMA_S8(acc[0][p], a0, bb[p]);
                MMA_S8(acc[1][p], a1, bb[p]);
            }
        }

        // fold finished code tile into running top-4, reset accumulators
        if (kc == CHUNKS - 1) {
            #pragma unroll
            for (int mt = 0; mt < 2; mt++) {
                #pragma unroll
                for (int p = 0; p < 8; p++) {
                    const int ng = nt * N_TILE + warpN * 64 + p * 8 + 2 * (lane & 3);
                    const float2 c2 = __ldg((const float2*)(g_c2s + ng));
                    t4_insert(t4v[mt * 2 + 0], t4i[mt * 2 + 0], c2.x - (float)acc[mt][p][0], ng);
                    t4_insert(t4v[mt * 2 + 0], t4i[mt * 2 + 0], c2.y - (float)acc[mt][p][1], ng + 1);
                    t4_insert(t4v[mt * 2 + 1], t4i[mt * 2 + 1], c2.x - (float)acc[mt][p][2], ng);
                    t4_insert(t4v[mt * 2 + 1], t4i[mt * 2 + 1], c2.y - (float)acc[mt][p][3], ng + 1);
                    acc[mt][p][0] = 0; acc[mt][p][1] = 0;
                    acc[mt][p][2] = 0; acc[mt][p][3] = 0;
                }
            }
        }
    }

    // ---- merge: quad (shfl) -> per-(row, warpN-half) top-4 -----------------
    #pragma unroll
    for (int rs = 0; rs < 4; rs++) {
        #pragma unroll
        for (int delta = 1; delta <= 2; delta <<= 1) {
            float ov[4]; int oi[4];
            #pragma unroll
            for (int j = 0; j < 4; j++) {
                ov[j] = __shfl_xor_sync(0xffffffffu, t4v[rs][j], delta);
                oi[j] = __shfl_xor_sync(0xffffffffu, t4i[rs][j], delta);
            }
            #pragma unroll
            for (int j = 0; j < 4; j++) t4_insert(t4v[rs], t4i[rs], ov[j], oi[j]);
        }
    }

    __syncthreads();  // all compute done: safe to alias B-stage smem
    int*   mi = (int*)(dsm + (Bb - sraw));            // 2 x 256 x 4 ints (8KB)
    float* mv = (float*)(dsm + (Bb - sraw) + 8192);   // 2 x 256 x 4 floats
    if ((lane & 3) == 0) {
        #pragma unroll
        for (int rs = 0; rs < 4; rs++) {
            int row_local = warpM * 32 + (rs >> 1) * 16 + ((rs & 1) << 3) + (lane >> 2);
            int idx = (warpN * 256 + row_local) * 4;
            #pragma unroll
            for (int j = 0; j < 4; j++) { mi[idx + j] = t4i[rs][j]; mv[idx + j] = t4v[rs][j]; }
        }
    }
    __syncthreads();
    // union of both halves' top-4 -> 8 candidates per row + scaled scores
    if (tid < 256) {
        #pragma unroll
        for (int j = 0; j < 4; j++) {
            g_cand[(size_t)(m0 + tid) * 8 + j]     = mi[tid * 4 + j];
            g_cand[(size_t)(m0 + tid) * 8 + 4 + j] = mi[(256 + tid) * 4 + j];
            g_csc[(size_t)(m0 + tid) * 8 + j]      = mv[tid * 4 + j];
            g_csc[(size_t)(m0 + tid) * 8 + 4 + j]  = mv[(256 + tid) * 4 + j];
        }
    }
}

// ---------------------------------------------------------------------------
// Kernel 2: margin-pruned exact fp32 rescore. Only candidates whose scaled
// score is within DELTA of the per-row scaled minimum get gathered (~1.5/row).
// Winner's codebook row is kept in registers -> no re-gather. Tie -> lower idx.
// out_near base only 8B aligned -> float2 stores.
// ---------------------------------------------------------------------------
__global__ void rescore_gather_kernel(const float* __restrict__ x,
                                      const float* __restrict__ cb,
                                      float* __restrict__ out_enc,
                                      float* __restrict__ out_near) {
    const int row = blockIdx.x;   // 32768
    const int t   = threadIdx.x;  // 128
    __shared__ float sdot[4];
    __shared__ float ws[4];

    int   cand[8];
    float sc[8];
    #pragma unroll
    for (int j = 0; j < 8; j++) {
        cand[j] = g_cand[(size_t)row * 8 + j];
        sc[j]   = g_csc[(size_t)row * 8 + j];
    }
    float smin = sc[0];
    #pragma unroll
    for (int j = 1; j < 8; j++) smin = fminf(smin, sc[j]);
    const float cut = smin + DELTA;

    const float4 xv = ((const float4*)(x + (size_t)row * DIM))[t];

    float  best = 3.4e38f;
    int    bi   = 0x7fffffff;
    float4 cbest = make_float4(0.f, 0.f, 0.f, 0.f);

    #pragma unroll
    for (int j = 0; j < 8; j++) {
        if (sc[j] > cut) continue;  // uniform across block (same sc/cut)
        const float4 cv = ((const float4*)(cb + (size_t)cand[j] * DIM))[t];
        float p = xv.x * cv.x + xv.y * cv.y + xv.z * cv.z + xv.w * cv.w;
        #pragma unroll
        for (int off = 16; off > 0; off >>= 1)
            p += __shfl_down_sync(0xffffffffu, p, off);
        if ((t & 31) == 0) sdot[t >> 5] = p;
        __syncthreads();
        float dot = sdot[0] + sdot[1] + sdot[2] + sdot[3];
        __syncthreads();
        float s = g_c2[cand[j]] - dot;
        if (s < best || (s == best && cand[j] < bi)) {
            best = s; bi = cand[j]; cbest = cv;
        }
    }

    if (t == 0) out_enc[row] = (float)bi;

    float2* orow = (float2*)(out_near + (size_t)row * DIM);
    orow[2 * t]     = make_float2(cbest.x, cbest.y);
    orow[2 * t + 1] = make_float2(cbest.z, cbest.w);
    float dx = xv.x - cbest.x, dy = xv.y - cbest.y;
    float dz = xv.z - cbest.z, dw = xv.w - cbest.w;
    float s = dx * dx + dy * dy + dz * dz + dw * dw;
    #pragma unroll
    for (int off = 16; off > 0; off >>= 1)
        s += __shfl_down_sync(0xffffffffu, s, off);
    if ((t & 31) == 0) ws[t >> 5] = s;
    __syncthreads();
    if (t == 0) {
        double tot = (double)ws[0] + (double)ws[1] + (double)ws[2] + (double)ws[3];
        atomicAdd(&g_loss, tot);
    }
}

__global__ void finalize_kernel(float* __restrict__ out_losses) {
    double mean = g_loss / ((double)N_ROWS * (double)DIM);
    out_losses[0] = (float)mean;
    out_losses[1] = (float)mean;
}

// ---------------------------------------------------------------------------
// Output layout (float32): [0,32768) encoding; [32768,32770) losses;
// [32770, ...) nearest (base only 8B aligned).
// ---------------------------------------------------------------------------
extern "C" void kernel_launch(void* const* d_in, const int* in_sizes, int n_in,
                              void* d_out, int out_size) {
    const float* x  = (const float*)d_in[0];
    const float* cb = (const float*)d_in[1];
    if (n_in >= 2 && in_sizes[0] == KCODES * DIM && in_sizes[1] == N_ROWS * DIM) {
        const float* tmp = x; x = cb; cb = tmp;
    }

    float* out        = (float*)d_out;
    float* out_enc    = out;
    float* out_losses = out + N_ROWS;
    float* out_near   = out + N_ROWS + 2;

    static int smem_set = 0;
    if (!smem_set) {
        cudaFuncSetAttribute(cand_kernel,
                             cudaFuncAttributeMaxDynamicSharedMemorySize, DYN_SMEM);
        smem_set = 1;
    }

    prep_cb<<<KCODES, 128>>>(cb);
    cand_kernel<<<GRID, NTHR, DYN_SMEM>>>(x);
    rescore_gather_kernel<<<N_ROWS, 128>>>(x, cb, out_enc, out_near);
    finalize_kernel<<<1, 1>>>(out_losses);
}